// round 3
// baseline (speedup 1.0000x reference)
#include <cuda_runtime.h>
#include <cuda_bf16.h>

// Problem constants
#define BATCH 64
#define NWIN  256
#define HDIM  768
// ALPHA = 1/HDIM, BETA = 0.1
#define C_AB (0.1f / 768.0f)   // ALPHA*BETA
#define C_EM 0.9f              // 1 - BETA
#define C_K1 0.1f
#define C_BP 1.2f
#define C_AVDL 50.0f

// Scratch (no allocations allowed): etdf accumulator, masks, packed id codes.
__device__ float g_etdf[BATCH * NWIN];
__device__ float g_qm[BATCH * NWIN];
__device__ float g_dm[BATCH * NWIN];
__device__ int   g_qc[BATCH * NWIN];
__device__ int   g_dc[BATCH * NWIN];

// ---------------------------------------------------------------------------
// Kernel 1: masks + packed codes + zero etdf.
// ids are in [0,32) (fit in 8 bits) -> pack 4 ids into one int for exact-match.
// ---------------------------------------------------------------------------
__global__ void prep_kernel(const int4* __restrict__ qids,
                            const int4* __restrict__ dids) {
    int idx = blockIdx.x * blockDim.x + threadIdx.x;
    if (idx >= BATCH * NWIN) return;
    int4 a = qids[idx];
    g_qm[idx] = (a.x | a.y | a.z | a.w) ? 1.0f : 0.0f;
    g_qc[idx] = (a.x) | (a.y << 8) | (a.z << 16) | (a.w << 24);
    int4 b = dids[idx];
    g_dm[idx] = (b.x | b.y | b.z | b.w) ? 1.0f : 0.0f;
    g_dc[idx] = (b.x) | (b.y << 8) | (b.z << 16) | (b.w << 24);
    g_etdf[idx] = 0.0f;
}

// ---------------------------------------------------------------------------
// Kernel 2: fused batched SGEMM 128x128x16 + epilogue
//   C[b,q,d] = dot(q_rep[b,q,:]*qm, d_rep[b,d,:]*dm)   -> written to out
//   etdf[b,q] += sum_d (C*ALPHA*BETA + em*(1-BETA)) * tf[b,d]
// Grid: (2, 2, 64), 256 threads, 8x8 microtile per thread.
// ---------------------------------------------------------------------------
__global__ void __launch_bounds__(256, 2) fused_gemm_kernel(
    const float* __restrict__ qrep, const float* __restrict__ drep,
    const int* __restrict__ dtfs, float* __restrict__ outmat) {

    const int b     = blockIdx.z;
    const int tmrow = blockIdx.y * 128;  // q-window tile base
    const int tncol = blockIdx.x * 128;  // d-window tile base

    __shared__ float As[2][16][128];
    __shared__ float Bs[2][16][128];

    const int tid  = threadIdx.x;
    const int lrow = tid >> 2;         // 0..63 (two row phases: +0, +64)
    const int lk   = (tid & 3) << 2;   // 0,4,8,12

    const float* Ag = qrep + ((size_t)b * NWIN + tmrow) * HDIM;
    const float* Bg = drep + ((size_t)b * NWIN + tncol) * HDIM;

    const int ty = tid >> 4;   // 0..15 -> rows ty*8..ty*8+7
    const int tx = tid & 15;   // 0..15 -> cols tx*8..tx*8+7

    float acc[8][8];
#pragma unroll
    for (int i = 0; i < 8; i++)
#pragma unroll
        for (int j = 0; j < 8; j++) acc[i][j] = 0.0f;

    // prologue: tile 0 -> buffer 0
    {
        float4 a0 = *(const float4*)(Ag + (size_t)lrow * HDIM + lk);
        float4 a1 = *(const float4*)(Ag + (size_t)(lrow + 64) * HDIM + lk);
        float4 b0 = *(const float4*)(Bg + (size_t)lrow * HDIM + lk);
        float4 b1 = *(const float4*)(Bg + (size_t)(lrow + 64) * HDIM + lk);
        As[0][lk + 0][lrow] = a0.x; As[0][lk + 1][lrow] = a0.y;
        As[0][lk + 2][lrow] = a0.z; As[0][lk + 3][lrow] = a0.w;
        As[0][lk + 0][lrow + 64] = a1.x; As[0][lk + 1][lrow + 64] = a1.y;
        As[0][lk + 2][lrow + 64] = a1.z; As[0][lk + 3][lrow + 64] = a1.w;
        Bs[0][lk + 0][lrow] = b0.x; Bs[0][lk + 1][lrow] = b0.y;
        Bs[0][lk + 2][lrow] = b0.z; Bs[0][lk + 3][lrow] = b0.w;
        Bs[0][lk + 0][lrow + 64] = b1.x; Bs[0][lk + 1][lrow + 64] = b1.y;
        Bs[0][lk + 2][lrow + 64] = b1.z; Bs[0][lk + 3][lrow + 64] = b1.w;
    }
    __syncthreads();

    const int NK = HDIM / 16;  // 48
    for (int kt = 0; kt < NK; kt++) {
        const int cb = kt & 1;
        float4 a0, a1, b0, b1;
        const bool more = (kt + 1 < NK);
        if (more) {
            const float* Ag2 = Ag + (kt + 1) * 16;
            const float* Bg2 = Bg + (kt + 1) * 16;
            a0 = *(const float4*)(Ag2 + (size_t)lrow * HDIM + lk);
            a1 = *(const float4*)(Ag2 + (size_t)(lrow + 64) * HDIM + lk);
            b0 = *(const float4*)(Bg2 + (size_t)lrow * HDIM + lk);
            b1 = *(const float4*)(Bg2 + (size_t)(lrow + 64) * HDIM + lk);
        }
#pragma unroll
        for (int k = 0; k < 16; k++) {
            float4 af0 = *(const float4*)&As[cb][k][ty * 8];
            float4 af1 = *(const float4*)&As[cb][k][ty * 8 + 4];
            float4 bf0 = *(const float4*)&Bs[cb][k][tx * 8];
            float4 bf1 = *(const float4*)&Bs[cb][k][tx * 8 + 4];
            float ar[8] = {af0.x, af0.y, af0.z, af0.w, af1.x, af1.y, af1.z, af1.w};
            float br[8] = {bf0.x, bf0.y, bf0.z, bf0.w, bf1.x, bf1.y, bf1.z, bf1.w};
#pragma unroll
            for (int i = 0; i < 8; i++)
#pragma unroll
                for (int j = 0; j < 8; j++) acc[i][j] = fmaf(ar[i], br[j], acc[i][j]);
        }
        if (more) {
            const int nb = cb ^ 1;
            As[nb][lk + 0][lrow] = a0.x; As[nb][lk + 1][lrow] = a0.y;
            As[nb][lk + 2][lrow] = a0.z; As[nb][lk + 3][lrow] = a0.w;
            As[nb][lk + 0][lrow + 64] = a1.x; As[nb][lk + 1][lrow + 64] = a1.y;
            As[nb][lk + 2][lrow + 64] = a1.z; As[nb][lk + 3][lrow + 64] = a1.w;
            Bs[nb][lk + 0][lrow] = b0.x; Bs[nb][lk + 1][lrow] = b0.y;
            Bs[nb][lk + 2][lrow] = b0.z; Bs[nb][lk + 3][lrow] = b0.w;
            Bs[nb][lk + 0][lrow + 64] = b1.x; Bs[nb][lk + 1][lrow + 64] = b1.y;
            Bs[nb][lk + 2][lrow + 64] = b1.z; Bs[nb][lk + 3][lrow + 64] = b1.w;
        }
        __syncthreads();
    }

    // ---- epilogue: mask, store, exact-match, tf-weighted row reduction ----
    const int gmb = b * NWIN + tmrow + ty * 8;  // global q index base
    const int gnb = b * NWIN + tncol + tx * 8;  // global d index base

    float dmask[8], tfab[8], tf9[8];
    int dc[8];
#pragma unroll
    for (int j = 0; j < 8; j++) {
        dmask[j] = g_dm[gnb + j];
        dc[j]    = g_dc[gnb + j];
        float tf = (float)dtfs[gnb + j];
        tfab[j]  = tf * C_AB;
        tf9[j]   = tf * C_EM;
    }

#pragma unroll
    for (int i = 0; i < 8; i++) {
        const float qmask = g_qm[gmb + i];
        const int   qc    = g_qc[gmb + i];
        float c[8];
        float psum = 0.0f;
#pragma unroll
        for (int j = 0; j < 8; j++) {
            float v = acc[i][j] * qmask * dmask[j];
            c[j] = v;
            psum += v * tfab[j];
            if (qc == dc[j]) psum += tf9[j];
        }
        // coalesced-ish 128-bit stores of this row's 8 outputs
        float* orow = outmat +
            ((size_t)(b * NWIN + tmrow + ty * 8 + i)) * NWIN + tncol + tx * 8;
        *(float4*)(orow + 0) = make_float4(c[0], c[1], c[2], c[3]);
        *(float4*)(orow + 4) = make_float4(c[4], c[5], c[6], c[7]);

        // reduce psum over the 16 tx lanes (bits 0..3 of lane id)
#pragma unroll
        for (int off = 8; off; off >>= 1)
            psum += __shfl_xor_sync(0xffffffffu, psum, off);
        if (tx == 0) atomicAdd(&g_etdf[gmb + i], psum);
    }
}

// ---------------------------------------------------------------------------
// Kernel 3: BM25 score per batch. One block per batch, 256 threads (one per w).
// ---------------------------------------------------------------------------
__global__ void score_kernel(const float* __restrict__ qtw,
                             const int* __restrict__ dtfs,
                             float* __restrict__ sout) {
    __shared__ float red[256];
    const int b = blockIdx.x;
    const int w = threadIdx.x;

    float tf = (float)dtfs[b * NWIN + w];
    red[w] = tf;
    __syncthreads();
#pragma unroll
    for (int off = 128; off; off >>= 1) {
        if (w < off) red[w] += red[w + off];
        __syncthreads();
    }
    const float dl = red[0];
    __syncthreads();

    const float e   = g_etdf[b * NWIN + w];
    const float nom = e + C_K1 * (1.0f - C_BP + C_BP * dl / C_AVDL);
    const float dtw = (e * (1.0f + C_K1)) / (nom + 1e-8f);
    float v = qtw[b * NWIN + w] * dtw;

    red[w] = v;
    __syncthreads();
#pragma unroll
    for (int off = 128; off; off >>= 1) {
        if (w < off) red[w] += red[w + off];
        __syncthreads();
    }
    if (w == 0) sout[b] = red[0];
}

// ---------------------------------------------------------------------------
extern "C" void kernel_launch(void* const* d_in, const int* in_sizes, int n_in,
                              void* d_out, int out_size) {
    const float* qrep = (const float*)d_in[0];  // [B, NW, H]
    const float* drep = (const float*)d_in[1];  // [B, NW, H]
    const float* qtw  = (const float*)d_in[2];  // [B, NW]
    const int4*  qids = (const int4*)d_in[3];   // [B, NW, 4]
    const int4*  dids = (const int4*)d_in[4];   // [B, NW, 4]
    const int*   dtfs = (const int*)d_in[5];    // [B, NW]

    float* out  = (float*)d_out;
    float* sout = out;            // s: [B]
    float* mat  = out + BATCH;    // d_expanded_tf: [B, NW, NW]

    prep_kernel<<<(BATCH * NWIN + 255) / 256, 256>>>(qids, dids);

    dim3 grid(2, 2, BATCH);
    fused_gemm_kernel<<<grid, 256>>>(qrep, drep, dtfs, mat);

    score_kernel<<<BATCH, 256>>>(qtw, dtfs, sout);
}

// round 7
// speedup vs baseline: 2.0716x; 2.0716x over previous
#include <cuda_runtime.h>
#include <cuda_bf16.h>
#include <cstdint>

// Problem constants
#define BATCH 64
#define NWIN  256
#define HDIM  768
#define C_AB   (0.1f / 768.0f)   // ALPHA*BETA
#define C_EM   0.9f              // 1 - BETA
#define C_K1   0.1f
#define C_BP   1.2f
#define C_AVDL 50.0f

// etdf accumulator (each (b,q) written exactly once; no zero-init needed)
__device__ float g_etdf[BATCH * NWIN];

// ---------------- SMEM layout ----------------
// Tiles use 80-byte row stride (32 bf16 = 64B data + 16B pad) -> conflict-free
// ldmatrix: row bases mod 128 = {0,80,32,112,64,16,96,48}, disjoint 16B segments.
#define TSTRIDE 80
#define AH_OFF  0
#define AL_OFF  (128 * TSTRIDE)              // 10240
#define BH_OFF  (2 * 128 * TSTRIDE)          // 20480
#define BL_OFF  (BH_OFF + 256 * TSTRIDE)     // 40960
#define STAGE_BYTES (BL_OFF + 256 * TSTRIDE) // 61440
#define TBL_OFF (2 * STAGE_BYTES)            // 122880
//   dm f[256] @ +0, tab f[256] @ +1024, tem f[256] @ +2048, dc i[256] @ +3072,
//   qm f[128] @ +4096, qc i[128] @ +4608
#define RED_OFF (TBL_OFF + 5120)             // red[4][128] floats
#define SMEM_TOTAL (RED_OFF + 2048)          // 130048 bytes

#define N_CHUNK 24      // 768 / 32
#define KCH     32      // K elements per chunk

static __device__ __forceinline__ uint32_t smem_u32(const void* p) {
    uint32_t a;
    asm("{ .reg .u64 t; cvta.to.shared.u64 t, %1; cvt.u32.u64 %0, t; }"
        : "=r"(a) : "l"(p));
    return a;
}

#define LDMX4(R, addr)                                                        \
    asm volatile("ldmatrix.sync.aligned.m8n8.x4.shared.b16 {%0,%1,%2,%3}, [%4];" \
                 : "=r"((R)[0]), "=r"((R)[1]), "=r"((R)[2]), "=r"((R)[3])     \
                 : "r"(addr))

#define MMA_BF16(D, A, B0, B1)                                                \
    asm volatile("mma.sync.aligned.m16n8k16.row.col.f32.bf16.bf16.f32 "       \
                 "{%0,%1,%2,%3}, {%4,%5,%6,%7}, {%8,%9}, {%0,%1,%2,%3};"      \
                 : "+f"((D)[0]), "+f"((D)[1]), "+f"((D)[2]), "+f"((D)[3])     \
                 : "r"((A)[0]), "r"((A)[1]), "r"((A)[2]), "r"((A)[3]),        \
                   "r"(B0), "r"(B1))

// ---------------------------------------------------------------------------
// Fused kernel: per-CTA 128x256 tile of one batch, hi/lo bf16 split GEMM via
// mma.sync (3 passes: ah*bh + al*bh + ah*bl), fused epilogue.
// 512 threads: warp (mi,ni) = (wid>>2, wid&3), warp tile 32x64.
// ---------------------------------------------------------------------------
__global__ void __launch_bounds__(512, 1) fused_kernel(
    const float* __restrict__ qrep, const float* __restrict__ drep,
    const int4* __restrict__ qids, const int4* __restrict__ dids,
    const int* __restrict__ dtfs, float* __restrict__ outmat) {

    extern __shared__ char smem[];
    const uint32_t sb = smem_u32(smem);

    const int tid  = threadIdx.x;
    const int lane = tid & 31;
    const int wid  = tid >> 5;
    const int mi   = wid >> 2;   // 0..3, warp M position (32 rows)
    const int ni   = wid & 3;    // 0..3, warp N position (64 cols)

    const int b     = blockIdx.x >> 1;
    const int tmrow = (blockIdx.x & 1) * 128;

    // ---- epilogue tables (written before first sync, read after mainloop) ----
    {
        float* dm_s  = (float*)(smem + TBL_OFF);
        float* tab_s = (float*)(smem + TBL_OFF + 1024);
        float* tem_s = (float*)(smem + TBL_OFF + 2048);
        int*   dc_s  = (int*)  (smem + TBL_OFF + 3072);
        float* qm_s  = (float*)(smem + TBL_OFF + 4096);
        int*   qc_s  = (int*)  (smem + TBL_OFF + 4608);
        if (tid < 256) {
            int4 di = dids[b * NWIN + tid];
            dm_s[tid] = (di.x | di.y | di.z | di.w) ? 1.0f : 0.0f;
            dc_s[tid] = di.x | (di.y << 8) | (di.z << 16) | (di.w << 24);
            float tf  = (float)dtfs[b * NWIN + tid];
            tab_s[tid] = tf * C_AB;
            tem_s[tid] = tf * C_EM;
        } else if (tid < 384) {
            int t = tid - 256;
            int4 qi = qids[b * NWIN + tmrow + t];
            qm_s[t] = (qi.x | qi.y | qi.z | qi.w) ? 1.0f : 0.0f;
            qc_s[t] = qi.x | (qi.y << 8) | (qi.z << 16) | (qi.w << 24);
        }
    }

    const float* Aep = qrep + (size_t)(b * NWIN + tmrow) * HDIM;
    const float* Bep = drep + (size_t)(b * NWIN) * HDIM;

    float acc[2][8][4];
#pragma unroll
    for (int mt = 0; mt < 2; mt++)
#pragma unroll
        for (int nt = 0; nt < 8; nt++)
#pragma unroll
            for (int e = 0; e < 4; e++) acc[mt][nt][e] = 0.0f;

    // task decode: 3072 float4 tasks/chunk (A:1024, B:2048), 6 per thread
    int trow[6], tkq[6];
    bool tisA[6];
#pragma unroll
    for (int i = 0; i < 6; i++) {
        int t = tid + i * 512;
        if (t < 1024) { tisA[i] = true;  trow[i] = t >> 3;  tkq[i] = t & 7; }
        else { int u = t - 1024; tisA[i] = false; trow[i] = u >> 3; tkq[i] = u & 7; }
    }

    float4 pf[6];

    // load chunk c into pf
    auto load_chunk = [&](int c) {
#pragma unroll
        for (int i = 0; i < 6; i++) {
            const float* base = tisA[i] ? Aep : Bep;
            pf[i] = *(const float4*)(base + (size_t)trow[i] * HDIM + c * KCH + tkq[i] * 4);
        }
    };
    // convert pf, store into stage s
    auto store_chunk = [&](int s) {
        char* stg = smem + s * STAGE_BYTES;
#pragma unroll
        for (int i = 0; i < 6; i++) {
            float4 f = pf[i];
            __nv_bfloat162 h01 = __floats2bfloat162_rn(f.x, f.y);
            __nv_bfloat162 h23 = __floats2bfloat162_rn(f.z, f.w);
            __nv_bfloat162 l01 = __floats2bfloat162_rn(f.x - __bfloat162float(h01.x),
                                                       f.y - __bfloat162float(h01.y));
            __nv_bfloat162 l23 = __floats2bfloat162_rn(f.z - __bfloat162float(h23.x),
                                                       f.w - __bfloat162float(h23.y));
            int off = trow[i] * TSTRIDE + tkq[i] * 8;
            char* ht = stg + (tisA[i] ? AH_OFF : BH_OFF) + off;
            char* lt = stg + (tisA[i] ? AL_OFF : BL_OFF) + off;
            union { __nv_bfloat162 h[2]; uint2 u; } H, L;
            H.h[0] = h01; H.h[1] = h23; L.h[0] = l01; L.h[1] = l23;
            *(uint2*)ht = H.u;
            *(uint2*)lt = L.u;
        }
    };

    // ldmatrix lane address components (80B stride rows)
    const int arow  = ((lane >> 3) & 1) * 8 + (lane & 7);  // m-row in 16-tile
    const int akoff = (lane >> 4) * 16;                    // 0 or 16 bytes (k 0-7 / 8-15)
    const int brow  = ((lane >> 4) & 1) * 8 + (lane & 7);  // n-row in 16-row pair
    const int bkoff = ((lane >> 3) & 1) * 16;
    const uint32_t aLane = (uint32_t)((mi * 32 + arow) * TSTRIDE + akoff);
    const uint32_t bLane = (uint32_t)((ni * 64 + brow) * TSTRIDE + bkoff);

    store_chunk(0);  // chunk 0 loaded below
    // NOTE: must load before store; do it properly:
    // (we loaded nothing yet) -> fix order:
    load_chunk(0);
    store_chunk(0);
    __syncthreads();

    for (int c = 0; c < N_CHUNK; c++) {
        const int s = c & 1;
        const bool more = (c + 1 < N_CHUNK);
        if (more) load_chunk(c + 1);

        const uint32_t stg = sb + s * STAGE_BYTES;
#pragma unroll
        for (int ks = 0; ks < 2; ks++) {
            uint32_t ah[2][4], al[2][4];
            const uint32_t aAddr = stg + aLane + ks * 32;
            LDMX4(ah[0], aAddr + AH_OFF);
            LDMX4(ah[1], aAddr + AH_OFF + 16 * TSTRIDE);
            LDMX4(al[0], aAddr + AL_OFF);
            LDMX4(al[1], aAddr + AL_OFF + 16 * TSTRIDE);
#pragma unroll
            for (int ntp = 0; ntp < 4; ntp++) {
                const uint32_t bAddr = stg + bLane + ntp * 16 * TSTRIDE + ks * 32;
                uint32_t bh[4], bl[4];
                LDMX4(bh, bAddr + BH_OFF);
                // hi*hi
                MMA_BF16(acc[0][2 * ntp],     ah[0], bh[0], bh[1]);
                MMA_BF16(acc[0][2 * ntp + 1], ah[0], bh[2], bh[3]);
                MMA_BF16(acc[1][2 * ntp],     ah[1], bh[0], bh[1]);
                MMA_BF16(acc[1][2 * ntp + 1], ah[1], bh[2], bh[3]);
                // lo*hi
                MMA_BF16(acc[0][2 * ntp],     al[0], bh[0], bh[1]);
                MMA_BF16(acc[0][2 * ntp + 1], al[0], bh[2], bh[3]);
                MMA_BF16(acc[1][2 * ntp],     al[1], bh[0], bh[1]);
                MMA_BF16(acc[1][2 * ntp + 1], al[1], bh[2], bh[3]);
                // hi*lo
                LDMX4(bl, bAddr + BL_OFF);
                MMA_BF16(acc[0][2 * ntp],     ah[0], bl[0], bl[1]);
                MMA_BF16(acc[0][2 * ntp + 1], ah[0], bl[2], bl[3]);
                MMA_BF16(acc[1][2 * ntp],     ah[1], bl[0], bl[1]);
                MMA_BF16(acc[1][2 * ntp + 1], ah[1], bl[2], bl[3]);
            }
        }
        if (more) store_chunk(s ^ 1);
        __syncthreads();
    }

    // ---------------- epilogue ----------------
    const float* dm_s  = (const float*)(smem + TBL_OFF);
    const float* tab_s = (const float*)(smem + TBL_OFF + 1024);
    const float* tem_s = (const float*)(smem + TBL_OFF + 2048);
    const int*   dc_s  = (const int*)  (smem + TBL_OFF + 3072);
    const float* qm_s  = (const float*)(smem + TBL_OFF + 4096);
    const int*   qc_s  = (const int*)  (smem + TBL_OFF + 4608);

    const int r4 = lane >> 2;          // 0..7
    const int c2 = (lane & 3) * 2;     // 0,2,4,6
    float psum[4];

#pragma unroll
    for (int mt = 0; mt < 2; mt++) {
#pragma unroll
        for (int rh = 0; rh < 2; rh++) {
            const int rl = mi * 32 + mt * 16 + rh * 8 + r4;   // local q row 0..127
            const float qm = qm_s[rl];
            const int   qc = qc_s[rl];
            float* orow = outmat + (size_t)(b * NWIN + tmrow + rl) * NWIN;
            float ps = 0.0f;
#pragma unroll
            for (int nt = 0; nt < 8; nt++) {
                const int col = ni * 64 + nt * 8 + c2;
                float v0 = acc[mt][nt][rh * 2 + 0] * qm * dm_s[col];
                float v1 = acc[mt][nt][rh * 2 + 1] * qm * dm_s[col + 1];
                ps += v0 * tab_s[col] + v1 * tab_s[col + 1];
                if (qc == dc_s[col])     ps += tem_s[col];
                if (qc == dc_s[col + 1]) ps += tem_s[col + 1];
                *(float2*)(orow + col) = make_float2(v0, v1);
            }
            psum[mt * 2 + rh] = ps;
        }
    }

    // reduce over the 4 lanes sharing each row (lane xor 1, 2)
#pragma unroll
    for (int p = 0; p < 4; p++) {
        psum[p] += __shfl_xor_sync(0xffffffffu, psum[p], 1);
        psum[p] += __shfl_xor_sync(0xffffffffu, psum[p], 2);
    }
    float* red = (float*)(smem + RED_OFF);   // [4 ni][128 rows]
    if ((lane & 3) == 0) {
#pragma unroll
        for (int mt = 0; mt < 2; mt++)
#pragma unroll
            for (int rh = 0; rh < 2; rh++)
                red[ni * 128 + mi * 32 + mt * 16 + rh * 8 + r4] = psum[mt * 2 + rh];
    }
    __syncthreads();
    if (tid < 128) {
        float e = red[tid] + red[128 + tid] + red[256 + tid] + red[384 + tid];
        g_etdf[b * NWIN + tmrow + tid] = e;
    }
}

// ---------------------------------------------------------------------------
// BM25 score per batch.
// ---------------------------------------------------------------------------
__global__ void score_kernel(const float* __restrict__ qtw,
                             const int* __restrict__ dtfs,
                             float* __restrict__ sout) {
    __shared__ float red[256];
    const int b = blockIdx.x;
    const int w = threadIdx.x;

    float tf = (float)dtfs[b * NWIN + w];
    red[w] = tf;
    __syncthreads();
#pragma unroll
    for (int off = 128; off; off >>= 1) {
        if (w < off) red[w] += red[w + off];
        __syncthreads();
    }
    const float dl = red[0];
    __syncthreads();

    const float e   = g_etdf[b * NWIN + w];
    const float nom = e + C_K1 * (1.0f - C_BP + C_BP * dl / C_AVDL);
    const float dtw = (e * (1.0f + C_K1)) / (nom + 1e-8f);
    float v = qtw[b * NWIN + w] * dtw;

    red[w] = v;
    __syncthreads();
#pragma unroll
    for (int off = 128; off; off >>= 1) {
        if (w < off) red[w] += red[w + off];
        __syncthreads();
    }
    if (w == 0) sout[b] = red[0];
}

// ---------------------------------------------------------------------------
extern "C" void kernel_launch(void* const* d_in, const int* in_sizes, int n_in,
                              void* d_out, int out_size) {
    const float* qrep = (const float*)d_in[0];  // [B, NW, H]
    const float* drep = (const float*)d_in[1];  // [B, NW, H]
    const float* qtw  = (const float*)d_in[2];  // [B, NW]
    const int4*  qids = (const int4*)d_in[3];   // [B, NW, 4]
    const int4*  dids = (const int4*)d_in[4];   // [B, NW, 4]
    const int*   dtfs = (const int*)d_in[5];    // [B, NW]

    float* out  = (float*)d_out;
    float* sout = out;            // s: [B]
    float* mat  = out + BATCH;    // d_expanded_tf: [B, NW, NW]

    static int configured = 0;
    if (!configured) {
        cudaFuncSetAttribute(fused_kernel,
                             cudaFuncAttributeMaxDynamicSharedMemorySize,
                             SMEM_TOTAL);
        configured = 1;
    }

    fused_kernel<<<BATCH * 2, 512, SMEM_TOTAL>>>(qrep, drep, qids, dids,
                                                 dtfs, mat);
    score_kernel<<<BATCH, 256>>>(qtw, dtfs, sout);
}